// round 6
// baseline (speedup 1.0000x reference)
#include <cuda_runtime.h>
#include <cuda_bf16.h>

// ---------------------------------------------------------------------------
// Problem constants
// ---------------------------------------------------------------------------
#define B_  256
#define T_  512
#define I_  64
#define H_  256
#define G4  1024          // 4*H

// Recurrent decomposition: 16 clusters x 8 CTAs; CTA = 32 units x 16 batches
#define CS   8
#define NCL  16
#define NB   16
#define UPC  32
#define WST  4128         // weight smem stride per unit, bytes (4096 + 32 pad)
#define SMEM_WBYTES (UPC * WST)            // 132096
#define SMEM_HBYTES (128 * NB * 8)         // 16384  (128 kp x 16 b x float2)
#define SMEM_REC    (SMEM_WBYTES + SMEM_HBYTES)
#define HXC  4096          // floats per cluster slice in g_hx

// ---------------------------------------------------------------------------
// Static device scratch
// ---------------------------------------------------------------------------
__device__ float g_xproj[(size_t)B_ * T_ * G4];   // 512 MB (both layers reuse)
__device__ float g_h1[(size_t)B_ * T_ * H_];      // 128 MB layer-0 h sequence
__device__ float g_h2last[B_ * H_];
__device__ float g_hx[2 * NCL * HXC];             // double-buffered h exchange

// ---------------------------------------------------------------------------
// helpers
// ---------------------------------------------------------------------------
__device__ __forceinline__ void fma2(unsigned long long& d, unsigned long long a,
                                     unsigned long long b) {
    asm("fma.rn.f32x2 %0, %1, %2, %0;" : "+l"(d) : "l"(a), "l"(b));
}
__device__ __forceinline__ float foldx2(unsigned long long v) {
    float2 f;
    asm("mov.b64 {%0, %1}, %2;" : "=f"(f.x), "=f"(f.y) : "l"(v));
    return f.x + f.y;
}
__device__ __forceinline__ float2 u2f(unsigned long long v) {
    float2 f;
    asm("mov.b64 {%0, %1}, %2;" : "=f"(f.x), "=f"(f.y) : "l"(v));
    return f;
}
__device__ __forceinline__ float sigm(float x) {
    return __fdividef(1.0f, 1.0f + __expf(-x));   // x<<0: expf=inf -> 0, ok
}
__device__ __forceinline__ float tanh_acc(float x) {
    float xc = fminf(fmaxf(x, -15.0f), 15.0f);
    float e  = __expf(2.0f * xc);
    return __fdividef(e - 1.0f, e + 1.0f);
}

// ---------------------------------------------------------------------------
// Input-projection GEMM: g_xproj[M][1024] = A[M][K] @ W[1024][K]^T + b1 + b2
// 128x128x16 tile, 256 threads, 8x8 thread tile, f32x2 over N (A dup in smem)
// ---------------------------------------------------------------------------
#define PBM  128
#define PBN  128
#define PBK  16
#define PBNP 132

__global__ __launch_bounds__(256, 2) void proj_gemm(
    const float* __restrict__ Ain, const float* __restrict__ W,
    const float* __restrict__ b1, const float* __restrict__ b2, int K)
{
    __shared__ float2 Asd[PBK * PBM];
    __shared__ float  Bss[PBK * PBNP];

    const float* A = Ain ? Ain : g_h1;
    const int tid = threadIdx.x;
    const int nb0 = blockIdx.x * PBN;
    const int mb0 = blockIdx.y * PBM;
    const int n0 = (tid & 15) * 8, m0 = (tid >> 4) * 8;

    unsigned long long acc[8][4];
#pragma unroll
    for (int i = 0; i < 8; i++)
#pragma unroll
        for (int j = 0; j < 4; j++) acc[i][j] = 0ull;

    for (int k0 = 0; k0 < K; k0 += PBK) {
#pragma unroll
        for (int q = 0; q < 2; q++) {
            int fid = tid * 2 + q;
            int row = fid >> 2;
            int kq  = fid & 3;
            float4 va = *(const float4*)(A + (size_t)(mb0 + row) * K + k0 + kq * 4);
            Asd[(kq * 4 + 0) * PBM + row] = make_float2(va.x, va.x);
            Asd[(kq * 4 + 1) * PBM + row] = make_float2(va.y, va.y);
            Asd[(kq * 4 + 2) * PBM + row] = make_float2(va.z, va.z);
            Asd[(kq * 4 + 3) * PBM + row] = make_float2(va.w, va.w);
            float4 vb = *(const float4*)(W + (size_t)(nb0 + row) * K + k0 + kq * 4);
            Bss[(kq * 4 + 0) * PBNP + row] = vb.x;
            Bss[(kq * 4 + 1) * PBNP + row] = vb.y;
            Bss[(kq * 4 + 2) * PBNP + row] = vb.z;
            Bss[(kq * 4 + 3) * PBNP + row] = vb.w;
        }
        __syncthreads();

#pragma unroll
        for (int k = 0; k < PBK; k++) {
            const ulonglong2* ap = (const ulonglong2*)(Asd + k * PBM + m0);
            ulonglong2 a01 = ap[0], a23 = ap[1], a45 = ap[2], a67 = ap[3];
            const ulonglong2* bp = (const ulonglong2*)(Bss + k * PBNP + n0);
            ulonglong2 b03 = bp[0], b47 = bp[1];
            unsigned long long av[8] = {a01.x, a01.y, a23.x, a23.y,
                                        a45.x, a45.y, a67.x, a67.y};
            unsigned long long bv[4] = {b03.x, b03.y, b47.x, b47.y};
#pragma unroll
            for (int mi = 0; mi < 8; mi++)
#pragma unroll
                for (int nj = 0; nj < 4; nj++)
                    fma2(acc[mi][nj], av[mi], bv[nj]);
        }
        __syncthreads();
    }

    float bias[8];
#pragma unroll
    for (int j = 0; j < 8; j++) bias[j] = b1[nb0 + n0 + j] + b2[nb0 + n0 + j];

#pragma unroll
    for (int mi = 0; mi < 8; mi++) {
        float2 v0 = u2f(acc[mi][0]), v1 = u2f(acc[mi][1]);
        float2 v2 = u2f(acc[mi][2]), v3 = u2f(acc[mi][3]);
        float4 o0 = make_float4(v0.x + bias[0], v0.y + bias[1],
                                v1.x + bias[2], v1.y + bias[3]);
        float4 o1 = make_float4(v2.x + bias[4], v2.y + bias[5],
                                v3.x + bias[6], v3.y + bias[7]);
        float* dst = g_xproj + (size_t)(mb0 + m0 + mi) * G4 + nb0 + n0;
        *(float4*)(dst)     = o0;
        *(float4*)(dst + 4) = o1;
    }
}

// ---------------------------------------------------------------------------
// Recurrent kernel: all 512 steps of one layer in one launch.
// Cluster ci: batches [16ci,16ci+16).  CTA rank r: units [32r,32r+32).
// Thread (u = tid>>3, pp = tid&7): unit, batch pair (2pp,2pp+1).
// f32x2 lanes = (even k, odd k) partial sums -> fold at step end.
// Weight smem: per unit u, per kp: 32B = {(i_k,i_k1),(f...),(g...),(o...)}.
// h smem/exchange: float pairs [kp][b]: (h_{2kp}(b), h_{2kp+1}(b)).
// ---------------------------------------------------------------------------
__global__ void __cluster_dims__(CS, 1, 1) __launch_bounds__(256, 1)
lstm_rec(const float* __restrict__ Whh, int mode)
{
    extern __shared__ float smbase[];
    char*  Wsm = (char*)smbase;
    float* hsm = smbase + SMEM_WBYTES / 4;

    const int tid = threadIdx.x;
    const int r   = blockIdx.x & (CS - 1);
    const int ci  = blockIdx.x >> 3;
    const int u   = tid >> 3;
    const int pp  = tid & 7;
    const int gu  = UPC * r + u;
    const int b0  = ci * NB;

    // ---- stage Whh slice into smem, k-pair gate layout ----
#pragma unroll 4
    for (int j = 0; j < 32; j++) {
        int id  = j * 256 + tid;       // 8192 float4 loads
        int kq  = id & 63;             // float4 within row (k = 4*kq)
        int row = id >> 6;             // 0..127
        int g   = row >> 5;
        int uu  = row & 31;
        float4 v = *(const float4*)(Whh + (size_t)(g * H_ + UPC * r + uu) * H_ + kq * 4);
        char* dst = Wsm + uu * WST + (2 * kq) * 32 + g * 8;
        *(float2*)(dst)      = make_float2(v.x, v.y);
        *(float2*)(dst + 32) = make_float2(v.z, v.w);
    }

    // ---- zero parity-0 exchange slice (redundant across CTAs, harmless) ----
    {
        float4 z4 = make_float4(0.f, 0.f, 0.f, 0.f);
        float4* zp = (float4*)(g_hx + ci * HXC);
#pragma unroll
        for (int j = 0; j < 4; j++) zp[tid + 256 * j] = z4;
    }
    __syncthreads();

    float c0 = 0.0f, c1 = 0.0f;
    const char* wp = Wsm + u * WST;
    const char* hp = (const char*)hsm + pp * 16;

    for (int t = 0; t < T_; t++) {
        const int par = t & 1;

        // all CTAs' publishes from t-1 visible (release/acquire, cluster scope)
        asm volatile("barrier.cluster.arrive.aligned;" ::: "memory");
        asm volatile("barrier.cluster.wait.aligned;"   ::: "memory");

        // xproj gate loads for this step (latency hidden under reload+matvec)
        const float* xb0 = g_xproj + ((size_t)(b0 + 2 * pp) * T_ + t) * G4 + gu;
        const float* xb1 = xb0 + (size_t)T_ * G4;
        float xi0 = xb0[0], xf0 = xb0[256], xg0 = xb0[512], xo0 = xb0[768];
        float xi1 = xb1[0], xf1 = xb1[256], xg1 = xb1[512], xo1 = xb1[768];

        // ---- reload h into smem; .cv bypasses (possibly stale) L1 ----
        {
            const float4* src = (const float4*)(g_hx + (par * NCL + ci) * HXC);
            float4* dst = (float4*)hsm;
#pragma unroll
            for (int j = 0; j < 4; j++) dst[tid + 256 * j] = __ldcv(src + tid + 256 * j);
        }
        __syncthreads();

        // ---- matvec: k-paired f32x2 partial sums ----
        unsigned long long ai0 = 0, af0 = 0, ag0 = 0, ao0 = 0;
        unsigned long long ai1 = 0, af1 = 0, ag1 = 0, ao1 = 0;
#pragma unroll 4
        for (int kp = 0; kp < 128; kp++) {
            ulonglong2 wif = *(const ulonglong2*)(wp + kp * 32);
            ulonglong2 wgo = *(const ulonglong2*)(wp + kp * 32 + 16);
            ulonglong2 hv  = *(const ulonglong2*)(hp + kp * 128);
            fma2(ai0, wif.x, hv.x); fma2(af0, wif.y, hv.x);
            fma2(ag0, wgo.x, hv.x); fma2(ao0, wgo.y, hv.x);
            fma2(ai1, wif.x, hv.y); fma2(af1, wif.y, hv.y);
            fma2(ag1, wgo.x, hv.y); fma2(ao1, wgo.y, hv.y);
        }

        // ---- cell ----
        float i0 = sigm(foldx2(ai0) + xi0), f0 = sigm(foldx2(af0) + xf0);
        float gg0 = tanh_acc(foldx2(ag0) + xg0), o0 = sigm(foldx2(ao0) + xo0);
        c0 = f0 * c0 + i0 * gg0;
        float h0 = o0 * tanh_acc(c0);

        float i1 = sigm(foldx2(ai1) + xi1), f1 = sigm(foldx2(af1) + xf1);
        float gg1 = tanh_acc(foldx2(ag1) + xg1), o1 = sigm(foldx2(ao1) + xo1);
        c1 = f1 * c1 + i1 * gg1;
        float h1 = o1 * tanh_acc(c1);

        // ---- publish h to other parity (layout matches hsm exactly) ----
        {
            float* dst = g_hx + ((par ^ 1) * NCL + ci) * HXC
                       + (gu >> 1) * 32 + 4 * pp + (gu & 1);
            dst[0] = h0;
            dst[2] = h1;
        }

        if (mode == 0) {
            float* hd = g_h1 + ((size_t)(b0 + 2 * pp) * T_ + t) * H_ + gu;
            hd[0]                  = h0;
            hd[(size_t)T_ * H_]    = h1;
        } else if (t == T_ - 1) {
            g_h2last[(b0 + 2 * pp) * H_ + gu]     = h0;
            g_h2last[(b0 + 2 * pp + 1) * H_ + gu] = h1;
        }
    }
}

// ---------------------------------------------------------------------------
// Final FC: out[b] = h2last[b] . Wfc + bfc
// ---------------------------------------------------------------------------
__global__ void fc_kernel(const float* __restrict__ Wfc,
                          const float* __restrict__ bfc,
                          float* __restrict__ outp)
{
    __shared__ float ws[H_];
    int tid = threadIdx.x;
    if (tid < H_) ws[tid] = Wfc[tid];
    __syncthreads();

    float s = bfc[0];
    const float* hb = g_h2last + tid * H_;
#pragma unroll 8
    for (int uu = 0; uu < H_; uu++) s += hb[uu] * ws[uu];
    outp[tid] = s;
}

// ---------------------------------------------------------------------------
// Launch
// ---------------------------------------------------------------------------
extern "C" void kernel_launch(void* const* d_in, const int* in_sizes, int n_in,
                              void* d_out, int out_size)
{
    const float* x    = (const float*)d_in[0];
    const float* Wih0 = (const float*)d_in[1];
    const float* Whh0 = (const float*)d_in[2];
    const float* bih0 = (const float*)d_in[3];
    const float* bhh0 = (const float*)d_in[4];
    const float* Wih1 = (const float*)d_in[5];
    const float* Whh1 = (const float*)d_in[6];
    const float* bih1 = (const float*)d_in[7];
    const float* bhh1 = (const float*)d_in[8];
    const float* Wfc  = (const float*)d_in[9];
    const float* bfc  = (const float*)d_in[10];
    float* out = (float*)d_out;

    static int smem_set = 0;
    if (!smem_set) {
        cudaFuncSetAttribute((const void*)lstm_rec,
                             cudaFuncAttributeMaxDynamicSharedMemorySize, SMEM_REC);
        smem_set = 1;
    }

    dim3 pgrid(G4 / PBN, (B_ * T_) / PBM);   // (8, 1024)

    proj_gemm<<<pgrid, 256>>>(x, Wih0, bih0, bhh0, I_);
    lstm_rec<<<NCL * CS, 256, SMEM_REC>>>(Whh0, 0);
    proj_gemm<<<pgrid, 256>>>(nullptr, Wih1, bih1, bhh1, H_);
    lstm_rec<<<NCL * CS, 256, SMEM_REC>>>(Whh1, 1);
    fc_kernel<<<1, 256>>>(Wfc, bfc, out);
}

// round 14
// speedup vs baseline: 1.1472x; 1.1472x over previous
#include <cuda_runtime.h>

// ---------------------------------------------------------------------------
// Problem constants
// ---------------------------------------------------------------------------
#define B_  256
#define T_  512
#define I_  64
#define H_  256
#define G4  1024          // 4*H

// Recurrent decomposition: 16 clusters x 8 CTAs; CTA = 32 units x 16 batches
#define CS   8
#define NCL  16
#define NB   16
#define UPC  32
#define HXC  4096         // floats per (parity, cluster) slice of g_hx (16KB)

// Shared memory layout for lstm_rec
//   W    : 128 kp x 1024B  ([kp][row] f32x2 k-pairs, SW128-swizzled rows)
//   H    : 128 kp x 128B   ([kp][bp] 16B = 2 batches' k-pair)  — matches g_hx
//   PART : 8 ks x 8KB      ([ks][b][r] f32 partial gate sums)
//   GSM  : 128 r x 64B     ([r][b] f32 reduced gates)
#define OF_W     0
#define OF_H     131072
#define OF_PART  147456
#define OF_GSM   212992
#define SMEM_REC 221184

// ---------------------------------------------------------------------------
// Static device scratch
// ---------------------------------------------------------------------------
__device__ float g_xproj[(size_t)B_ * T_ * G4];   // 512 MB (both layers reuse)
__device__ float g_h1[(size_t)B_ * T_ * H_];      // 128 MB layer-0 h sequence
__device__ float g_h2last[B_ * H_];
__device__ float g_hx[2 * NCL * HXC];             // double-buffered h exchange

// ---------------------------------------------------------------------------
// helpers
// ---------------------------------------------------------------------------
__device__ __forceinline__ void fma2(unsigned long long& d, unsigned long long a,
                                     unsigned long long b) {
    asm("fma.rn.f32x2 %0, %1, %2, %0;" : "+l"(d) : "l"(a), "l"(b));
}
__device__ __forceinline__ float foldx2(unsigned long long v) {
    float2 f;
    asm("mov.b64 {%0, %1}, %2;" : "=f"(f.x), "=f"(f.y) : "l"(v));
    return f.x + f.y;
}
__device__ __forceinline__ float2 u2f(unsigned long long v) {
    float2 f;
    asm("mov.b64 {%0, %1}, %2;" : "=f"(f.x), "=f"(f.y) : "l"(v));
    return f;
}
__device__ __forceinline__ float sigm(float x) {
    return __fdividef(1.0f, 1.0f + __expf(-x));   // x<<0: expf=inf -> 0, ok
}
__device__ __forceinline__ float tanh_acc(float x) {
    float xc = fminf(fmaxf(x, -15.0f), 15.0f);
    float e  = __expf(2.0f * xc);
    return __fdividef(e - 1.0f, e + 1.0f);
}
__device__ __forceinline__ unsigned swz(unsigned o) {     // SW128 xor swizzle
    return o ^ ((o >> 3) & 0x70);
}

// ---------------------------------------------------------------------------
// Input-projection GEMM: g_xproj[M][1024] = A[M][K] @ W[1024][K]^T + b1 + b2
// (unchanged from the passing R6 kernel)
// ---------------------------------------------------------------------------
#define PBM  128
#define PBN  128
#define PBK  16
#define PBNP 132

__global__ __launch_bounds__(256, 2) void proj_gemm(
    const float* __restrict__ Ain, const float* __restrict__ W,
    const float* __restrict__ b1, const float* __restrict__ b2, int K)
{
    __shared__ float2 Asd[PBK * PBM];
    __shared__ float  Bss[PBK * PBNP];

    const float* A = Ain ? Ain : g_h1;
    const int tid = threadIdx.x;
    const int nb0 = blockIdx.x * PBN;
    const int mb0 = blockIdx.y * PBM;
    const int n0 = (tid & 15) * 8, m0 = (tid >> 4) * 8;

    unsigned long long acc[8][4];
#pragma unroll
    for (int i = 0; i < 8; i++)
#pragma unroll
        for (int j = 0; j < 4; j++) acc[i][j] = 0ull;

    for (int k0 = 0; k0 < K; k0 += PBK) {
#pragma unroll
        for (int q = 0; q < 2; q++) {
            int fid = tid * 2 + q;
            int row = fid >> 2;
            int kq  = fid & 3;
            float4 va = *(const float4*)(A + (size_t)(mb0 + row) * K + k0 + kq * 4);
            Asd[(kq * 4 + 0) * PBM + row] = make_float2(va.x, va.x);
            Asd[(kq * 4 + 1) * PBM + row] = make_float2(va.y, va.y);
            Asd[(kq * 4 + 2) * PBM + row] = make_float2(va.z, va.z);
            Asd[(kq * 4 + 3) * PBM + row] = make_float2(va.w, va.w);
            float4 vb = *(const float4*)(W + (size_t)(nb0 + row) * K + k0 + kq * 4);
            Bss[(kq * 4 + 0) * PBNP + row] = vb.x;
            Bss[(kq * 4 + 1) * PBNP + row] = vb.y;
            Bss[(kq * 4 + 2) * PBNP + row] = vb.z;
            Bss[(kq * 4 + 3) * PBNP + row] = vb.w;
        }
        __syncthreads();

#pragma unroll
        for (int k = 0; k < PBK; k++) {
            const ulonglong2* ap = (const ulonglong2*)(Asd + k * PBM + m0);
            ulonglong2 a01 = ap[0], a23 = ap[1], a45 = ap[2], a67 = ap[3];
            const ulonglong2* bp = (const ulonglong2*)(Bss + k * PBNP + n0);
            ulonglong2 b03 = bp[0], b47 = bp[1];
            unsigned long long av[8] = {a01.x, a01.y, a23.x, a23.y,
                                        a45.x, a45.y, a67.x, a67.y};
            unsigned long long bv[4] = {b03.x, b03.y, b47.x, b47.y};
#pragma unroll
            for (int mi = 0; mi < 8; mi++)
#pragma unroll
                for (int nj = 0; nj < 4; nj++)
                    fma2(acc[mi][nj], av[mi], bv[nj]);
        }
        __syncthreads();
    }

    float bias[8];
#pragma unroll
    for (int j = 0; j < 8; j++) bias[j] = b1[nb0 + n0 + j] + b2[nb0 + n0 + j];

#pragma unroll
    for (int mi = 0; mi < 8; mi++) {
        float2 v0 = u2f(acc[mi][0]), v1 = u2f(acc[mi][1]);
        float2 v2 = u2f(acc[mi][2]), v3 = u2f(acc[mi][3]);
        float4 o0 = make_float4(v0.x + bias[0], v0.y + bias[1],
                                v1.x + bias[2], v1.y + bias[3]);
        float4 o1 = make_float4(v2.x + bias[4], v2.y + bias[5],
                                v3.x + bias[6], v3.y + bias[7]);
        float* dst = g_xproj + (size_t)(mb0 + m0 + mi) * G4 + nb0 + n0;
        *(float4*)(dst)     = o0;
        *(float4*)(dst + 4) = o1;
    }
}

// ---------------------------------------------------------------------------
// Recurrent kernel: k-sliced register-tile matvec (fp32, FMA-bound design).
// Cluster ci: batches [16ci,16ci+16).  CTA rank r: rows = gate*32+u, u local.
// Matvec thread = (rg 0..15, bg 0..1, ks=warp 0..7):
//   8 rows x 8 batches f32x2 (even-k, odd-k) accumulators over 16 k-pairs.
// Partials reduced over ks via smem; cell thread = (u = tid>>3, pp = tid&7).
// h exchange layout [kp][bp] identical to the R6-passing kernel.
// ---------------------------------------------------------------------------
__global__ void __cluster_dims__(CS, 1, 1) __launch_bounds__(256, 1)
lstm_rec(const float* __restrict__ Whh, int mode)
{
    extern __shared__ char sm[];

    const int tid = threadIdx.x;
    const int wid = tid >> 5;          // = k-slice ks
    const int lid = tid & 31;
    const int rg  = lid >> 1;          // row-group 0..15 (rows 8rg..8rg+7)
    const int bg  = lid & 1;           // batch half (batches 8bg..8bg+7)
    const int r   = blockIdx.x & (CS - 1);
    const int ci  = blockIdx.x >> 3;
    const int u   = tid >> 3;          // cell phase: local unit
    const int pp  = tid & 7;           // cell phase: batch pair
    const int gu  = UPC * r + u;
    const int b0  = ci * NB;

    // ---- stage Whh slice into smem: [kp][row] f32x2, swizzled rows ----
#pragma unroll 4
    for (int j = 0; j < 32; j++) {
        int id  = j * 256 + tid;       // 8192 float4 loads
        int kq  = id & 63;             // k = 4*kq
        int m   = id >> 6;             // row 0..127 = g*32 + uu
        int g   = m >> 5, uu = m & 31;
        float4 v = *(const float4*)(Whh + (size_t)(g * H_ + UPC * r + uu) * H_ + kq * 4);
        unsigned ro = swz((unsigned)(m * 8));
        *(float2*)(sm + OF_W + (2 * kq) * 1024 + ro)     = make_float2(v.x, v.y);
        *(float2*)(sm + OF_W + (2 * kq + 1) * 1024 + ro) = make_float2(v.z, v.w);
    }

    // ---- zero parity-0 exchange slice ----
    {
        float4 z4 = make_float4(0.f, 0.f, 0.f, 0.f);
        float4* zp = (float4*)(g_hx + ci * HXC);
#pragma unroll
        for (int j = 0; j < 4; j++) zp[tid + 256 * j] = z4;
    }
    __syncthreads();

    // per-thread constant smem offsets
    unsigned wof[4], hof[4];
#pragma unroll
    for (int j = 0; j < 4; j++) {
        wof[j] = swz((unsigned)(rg * 64 + j * 16));
        hof[j] = (unsigned)((bg * 4 + j) * 16);
    }

    float c0 = 0.0f, c1 = 0.0f;

    for (int t = 0; t < T_; t++) {
        const int par = t & 1;

        // h[t] complete cluster-wide (release/acquire orders gmem exchange)
        asm volatile("barrier.cluster.arrive.aligned;" ::: "memory");
        asm volatile("barrier.cluster.wait.aligned;"   ::: "memory");

        // ---- prefetch xproj for this step (consumed in cell phase) ----
        float xp0[4], xp1[4];
        {
            const float* xb = g_xproj + ((size_t)(b0 + 2 * pp) * T_ + t) * G4 + gu;
            const float* xc = xb + (size_t)T_ * G4;
#pragma unroll
            for (int g = 0; g < 4; g++) { xp0[g] = xb[g * 256]; xp1[g] = xc[g * 256]; }
        }

        // ---- reload h into smem (verbatim 16KB copy, .cv dodges stale L1) ----
        {
            const uint4* src = (const uint4*)(g_hx + (par * NCL + ci) * HXC);
            uint4* dst = (uint4*)(sm + OF_H);
#pragma unroll
            for (int j = 0; j < 4; j++) dst[tid + 256 * j] = __ldcv(src + tid + 256 * j);
        }
        __syncthreads();

        // ---- matvec: 8x8 register tile over this warp's 16 k-pairs ----
        unsigned long long acc[8][8];
#pragma unroll
        for (int a = 0; a < 8; a++)
#pragma unroll
            for (int b = 0; b < 8; b++) acc[a][b] = 0ull;

#pragma unroll 2
        for (int i = 0; i < 16; i++) {
            const char* wk = sm + OF_W + (wid * 16 + i) * 1024;
            const char* hk = sm + OF_H + (wid * 16 + i) * 128;
            ulonglong2 w0 = *(const ulonglong2*)(wk + wof[0]);
            ulonglong2 w1 = *(const ulonglong2*)(wk + wof[1]);
            ulonglong2 w2 = *(const ulonglong2*)(wk + wof[2]);
            ulonglong2 w3 = *(const ulonglong2*)(wk + wof[3]);
            ulonglong2 h0 = *(const ulonglong2*)(hk + hof[0]);
            ulonglong2 h1 = *(const ulonglong2*)(hk + hof[1]);
            ulonglong2 h2 = *(const ulonglong2*)(hk + hof[2]);
            ulonglong2 h3 = *(const ulonglong2*)(hk + hof[3]);
            unsigned long long wv[8] = {w0.x, w0.y, w1.x, w1.y,
                                        w2.x, w2.y, w3.x, w3.y};
            unsigned long long hv[8] = {h0.x, h0.y, h1.x, h1.y,
                                        h2.x, h2.y, h3.x, h3.y};
#pragma unroll
            for (int a = 0; a < 8; a++)
#pragma unroll
                for (int b = 0; b < 8; b++)
                    fma2(acc[a][b], wv[a], hv[b]);
        }

        // ---- fold (even+odd k) and store partials: part[ks][b][r] ----
#pragma unroll
        for (int b = 0; b < 8; b++) {
            float4 v0, v1;
            v0.x = foldx2(acc[0][b]); v0.y = foldx2(acc[1][b]);
            v0.z = foldx2(acc[2][b]); v0.w = foldx2(acc[3][b]);
            v1.x = foldx2(acc[4][b]); v1.y = foldx2(acc[5][b]);
            v1.z = foldx2(acc[6][b]); v1.w = foldx2(acc[7][b]);
            char* pa = sm + OF_PART + wid * 8192 + (bg * 8 + b) * 512 + rg * 32;
            *(float4*)(pa)      = v0;
            *(float4*)(pa + 16) = v1;
        }
        __syncthreads();

        // ---- reduce over 8 k-slices -> gsm[r][b] ----
        {
            int rout = tid >> 1;
            int bh   = tid & 1;
            float o[8];
#pragma unroll
            for (int jb = 0; jb < 8; jb++) {
                const char* pa = sm + OF_PART + (bh * 8 + jb) * 512 + rout * 4;
                float s = 0.0f;
#pragma unroll
                for (int ks = 0; ks < 8; ks++)
                    s += *(const float*)(pa + ks * 8192);
                o[jb] = s;
            }
            char* ga = sm + OF_GSM + rout * 64 + bh * 32;
            *(float4*)(ga)      = make_float4(o[0], o[1], o[2], o[3]);
            *(float4*)(ga + 16) = make_float4(o[4], o[5], o[6], o[7]);
        }
        __syncthreads();

        // ---- cell update: thread (u, pp) -> batches 2pp, 2pp+1 ----
        float2 gi = *(float2*)(sm + OF_GSM + (0 * 32 + u) * 64 + pp * 8);
        float2 gf = *(float2*)(sm + OF_GSM + (1 * 32 + u) * 64 + pp * 8);
        float2 gg = *(float2*)(sm + OF_GSM + (2 * 32 + u) * 64 + pp * 8);
        float2 go = *(float2*)(sm + OF_GSM + (3 * 32 + u) * 64 + pp * 8);

        float i0 = sigm(gi.x + xp0[0]), f0 = sigm(gf.x + xp0[1]);
        float g0 = tanh_acc(gg.x + xp0[2]), o0 = sigm(go.x + xp0[3]);
        c0 = f0 * c0 + i0 * g0;
        float h0 = o0 * tanh_acc(c0);

        float i1 = sigm(gi.y + xp1[0]), f1 = sigm(gf.y + xp1[1]);
        float g1 = tanh_acc(gg.y + xp1[2]), o1 = sigm(go.y + xp1[3]);
        c1 = f1 * c1 + i1 * g1;
        float h1 = o1 * tanh_acc(c1);

        // ---- publish h to other parity (layout matches OF_H exactly) ----
        {
            float* dst = g_hx + ((par ^ 1) * NCL + ci) * HXC
                       + (gu >> 1) * 32 + 4 * pp + (gu & 1);
            dst[0] = h0;
            dst[2] = h1;
        }

        if (mode == 0) {
            float* hd = g_h1 + ((size_t)(b0 + 2 * pp) * T_ + t) * H_ + gu;
            hd[0]               = h0;
            hd[(size_t)T_ * H_] = h1;
        } else if (t == T_ - 1) {
            g_h2last[(b0 + 2 * pp) * H_ + gu]     = h0;
            g_h2last[(b0 + 2 * pp + 1) * H_ + gu] = h1;
        }
    }
}

// ---------------------------------------------------------------------------
// Final FC: out[b] = h2last[b] . Wfc + bfc
// ---------------------------------------------------------------------------
__global__ void fc_kernel(const float* __restrict__ Wfc,
                          const float* __restrict__ bfc,
                          float* __restrict__ outp)
{
    __shared__ float ws[H_];
    int tid = threadIdx.x;
    if (tid < H_) ws[tid] = Wfc[tid];
    __syncthreads();

    float s = bfc[0];
    const float* hb = g_h2last + tid * H_;
#pragma unroll 8
    for (int uu = 0; uu < H_; uu++) s += hb[uu] * ws[uu];
    outp[tid] = s;
}

// ---------------------------------------------------------------------------
// Launch
// ---------------------------------------------------------------------------
extern "C" void kernel_launch(void* const* d_in, const int* in_sizes, int n_in,
                              void* d_out, int out_size)
{
    const float* x    = (const float*)d_in[0];
    const float* Wih0 = (const float*)d_in[1];
    const float* Whh0 = (const float*)d_in[2];
    const float* bih0 = (const float*)d_in[3];
    const float* bhh0 = (const float*)d_in[4];
    const float* Wih1 = (const float*)d_in[5];
    const float* Whh1 = (const float*)d_in[6];
    const float* bih1 = (const float*)d_in[7];
    const float* bhh1 = (const float*)d_in[8];
    const float* Wfc  = (const float*)d_in[9];
    const float* bfc  = (const float*)d_in[10];
    float* out = (float*)d_out;

    cudaFuncSetAttribute((const void*)lstm_rec,
                         cudaFuncAttributeMaxDynamicSharedMemorySize, SMEM_REC);

    dim3 pgrid(G4 / PBN, (B_ * T_) / PBM);   // (8, 1024)

    proj_gemm<<<pgrid, 256>>>(x, Wih0, bih0, bhh0, I_);
    lstm_rec<<<NCL * CS, 256, SMEM_REC>>>(Whh0, 0);
    proj_gemm<<<pgrid, 256>>>(nullptr, Wih1, bih1, bhh1, H_);
    lstm_rec<<<NCL * CS, 256, SMEM_REC>>>(Whh1, 1);
    fc_kernel<<<1, 256>>>(Wfc, bfc, out);
}